// round 1
// baseline (speedup 1.0000x reference)
#include <cuda_runtime.h>

#ifndef EPSF
#define EPSF 1e-07f
#endif

static __device__ double g_acc;

__global__ void zero_acc_kernel() {
    g_acc = 0.0;
}

__global__ void __launch_bounds__(256)
ciou_reduce_kernel(const float4* __restrict__ pred,
                   const float4* __restrict__ targ,
                   int n) {
    float local = 0.0f;
    int stride = gridDim.x * blockDim.x;
    for (int i = blockIdx.x * blockDim.x + threadIdx.x; i < n; i += stride) {
        float4 p = pred[i];
        float4 t = targ[i];
        // p = (x1, y1, x2, y2)
        float px1 = p.x, py1 = p.y, px2 = p.z, py2 = p.w;
        float tx1 = t.x, ty1 = t.y, tx2 = t.z, ty2 = t.w;

        float iw = fminf(px2, tx2) - fmaxf(px1, tx1);
        float ih = fminf(py2, ty2) - fmaxf(py1, ty1);
        iw = fmaxf(iw, 0.0f);
        ih = fmaxf(ih, 0.0f);
        float inter = iw * ih;

        float pw = px2 - px1, ph = py2 - py1;
        float tw = tx2 - tx1, th = ty2 - ty1;
        float p_area = pw * ph;
        float t_area = tw * th;
        float iou = inter / (p_area + t_area - inter + EPSF);

        float dcx = 0.5f * (px1 + px2) - 0.5f * (tx1 + tx2);
        float dcy = 0.5f * (py1 + py2) - 0.5f * (ty1 + ty2);
        float center_dist_sq = dcx * dcx + dcy * dcy;

        float cw = fmaxf(px2, tx2) - fminf(px1, tx1);
        float ch = fmaxf(py2, ty2) - fminf(py1, ty1);
        float c_diag_sq = cw * cw + ch * ch + EPSF;      // eps inside bbox_iou
        float center_term = center_dist_sq / (c_diag_sq + EPSF);  // eps again in forward()

        float sw = (pw - tw) / (tw + EPSF);
        float sh = (ph - th) / (th + EPSF);
        float size_term = sw * sw + sh * sh;

        local += (1.0f - iou) + 2.0f * center_term + size_term;
    }

    // warp reduce
    #pragma unroll
    for (int off = 16; off > 0; off >>= 1)
        local += __shfl_down_sync(0xFFFFFFFFu, local, off);

    __shared__ float warp_sums[8];
    int lane = threadIdx.x & 31;
    int wid  = threadIdx.x >> 5;
    if (lane == 0) warp_sums[wid] = local;
    __syncthreads();

    if (wid == 0) {
        float v = (lane < (blockDim.x >> 5)) ? warp_sums[lane] : 0.0f;
        #pragma unroll
        for (int off = 4; off > 0; off >>= 1)
            v += __shfl_down_sync(0xFFFFFFFFu, v, off);
        if (lane == 0)
            atomicAdd(&g_acc, (double)v);
    }
}

__global__ void finalize_kernel(float* __restrict__ out, int n) {
    out[0] = (float)(g_acc / (double)n);
}

extern "C" void kernel_launch(void* const* d_in, const int* in_sizes, int n_in,
                              void* d_out, int out_size) {
    const float4* pred = (const float4*)d_in[0];
    const float4* targ = (const float4*)d_in[1];
    int n = in_sizes[0] / 4;  // in_sizes counts floats; 4 per box

    zero_acc_kernel<<<1, 1>>>();

    const int threads = 256;
    int blocks = (n + threads * 4 - 1) / (threads * 4);  // ~4 boxes per thread
    if (blocks > 4096) blocks = 4096;
    ciou_reduce_kernel<<<blocks, threads>>>(pred, targ, n);

    finalize_kernel<<<1, 1>>>((float*)d_out, n);
}